// round 16
// baseline (speedup 1.0000x reference)
#include <cuda_runtime.h>
#include <cuda_bf16.h>
#include <math.h>
#include <stdint.h>

// Problem constants
#define BB   128
#define QL   32
#define DL   1024
#define HH   768
#define DIMD 128
#define NEGV (-100000.0f)

// Scratch
__device__ __nv_bfloat16 g_Wbf[DIMD * HH];   // bf16 copy of W

// ---------------------------------------------------------------------------
// Helpers (base-ISA sm_80+)
// ---------------------------------------------------------------------------
__device__ __forceinline__ unsigned smem_u32(const void* p) {
    return (unsigned)__cvta_generic_to_shared(p);
}
__device__ __forceinline__ void cp_async16(unsigned dst, const void* src) {
    asm volatile("cp.async.cg.shared.global [%0], [%1], 16;\n" :: "r"(dst), "l"(src));
}
__device__ __forceinline__ void cp_commit() {
    asm volatile("cp.async.commit_group;\n" ::: "memory");
}
__device__ __forceinline__ void cp_wait2() {
    asm volatile("cp.async.wait_group 2;\n" ::: "memory");
}
__device__ __forceinline__ void bar_sync_n(int id) {
    asm volatile("bar.sync %0, 512;" :: "r"(id) : "memory");
}
__device__ __forceinline__ void bar_arrive_n(int id) {
    asm volatile("bar.arrive %0, 512;" :: "r"(id) : "memory");
}
__device__ __forceinline__ uint32_t f2bf2(float lo, float hi) {
    uint32_t r;
    asm("cvt.rn.bf16x2.f32 %0, %1, %2;" : "=r"(r) : "f"(hi), "f"(lo));
    return r;
}
__device__ __forceinline__ void ldsm_x4(uint32_t* r, uint32_t addr) {
    asm volatile("ldmatrix.sync.aligned.m8n8.x4.shared.b16 {%0,%1,%2,%3}, [%4];"
                 : "=r"(r[0]), "=r"(r[1]), "=r"(r[2]), "=r"(r[3]) : "r"(addr));
}
__device__ __forceinline__ void sts128(uint32_t addr, uint32_t r0, uint32_t r1,
                                       uint32_t r2, uint32_t r3) {
    asm volatile("st.shared.v4.b32 [%0], {%1,%2,%3,%4};"
                 :: "r"(addr), "r"(r0), "r"(r1), "r"(r2), "r"(r3) : "memory");
}
__device__ __forceinline__ void sts32(uint32_t addr, uint32_t r0) {
    asm volatile("st.shared.b32 [%0], %1;" :: "r"(addr), "r"(r0) : "memory");
}
__device__ __forceinline__ void mma_bf16(float* c, const uint32_t* a, const uint32_t* b) {
    asm volatile(
        "mma.sync.aligned.m16n8k16.row.col.f32.bf16.bf16.f32 "
        "{%0,%1,%2,%3}, {%4,%5,%6,%7}, {%8,%9}, {%0,%1,%2,%3};"
        : "+f"(c[0]), "+f"(c[1]), "+f"(c[2]), "+f"(c[3])
        : "r"(a[0]), "r"(a[1]), "r"(a[2]), "r"(a[3]), "r"(b[0]), "r"(b[1]));
}

// ---------------------------------------------------------------------------
// Kernel 0: W fp32 -> bf16
// ---------------------------------------------------------------------------
__global__ void wconv_kernel(const float* __restrict__ W)
{
    int i = blockIdx.x * 256 + threadIdx.x;
    float4 v = *(const float4*)(W + (size_t)i * 4);
    *(uint2*)((char*)g_Wbf + (size_t)i * 8) = make_uint2(f2bf2(v.x, v.y), f2bf2(v.z, v.w));
}

// ---------------------------------------------------------------------------
// Fused kernel, warp-specialized mainloop.
// 128 CTAs (one batch), 512 threads: warps 0-7 consumers (MMA, warp tile
// 32x64), warps 8-15 producers (A LDG+cvt+STS, W cp.async).
// Named barriers: AF (ids 1-3) A/W full, AE (4-6) A empty, WE (7-10) W empty.
//
// SMEM bytes:
//   Qbf   0       8704    (32 x 128 bf16, stride 272)
//   Dbf   8704    34816   (128 x 128 bf16, stride 272)
//   A0-2  43520   3*18432 (128 x 64 bf16, stride 144)
//   W0-3  98816   4*18432
//   rs    172544  1024    (2 x 128 f32)
//   dsq   173568  512
//   qsq   174080  128
//   qpart 174208  1024
//   idx   175232  4096
//   cnt   179328  128
//   total 179456
// ---------------------------------------------------------------------------
#define SM_QBF   0
#define SM_DBF   8704
#define SM_A0    43520
#define SM_A1    61952
#define SM_A2    80384
#define SM_W0    98816
#define SM_W1    117248
#define SM_W2    135680
#define SM_W3    154112
#define SM_RS    172544
#define SM_DSQ   173568
#define SM_QSQ   174080
#define SM_QPART 174208
#define SM_IDX   175232
#define SM_CNT   179328
#define SM_TOTAL 179456

#define RSTR    144          // A/W row stride (64 bf16 + pad)
#define QSTR    272          // Qbf/Dbf row stride (128 bf16 + pad)
#define KC      64
#define NCHUNK  (HH / KC)    // 12

__global__ __launch_bounds__(512, 1)
void score_kernel(const float* __restrict__ Demb,
                  const float* __restrict__ Qe,
                  const int*   __restrict__ ids,
                  const int*   __restrict__ attn,
                  float*       __restrict__ out)
{
    extern __shared__ char smc[];
    float* rs    = (float*)(smc + SM_RS);
    float* dsq   = (float*)(smc + SM_DSQ);
    float* qsq   = (float*)(smc + SM_QSQ);
    float* qpart = (float*)(smc + SM_QPART);
    int*   idx_s = (int*)  (smc + SM_IDX);
    int*   cnt_s = (int*)  (smc + SM_CNT);

    const uint32_t base = smem_u32(smc);

    const int b    = blockIdx.x;
    const int tid  = threadIdx.x;
    const int lane = tid & 31;
    const int warp = tid >> 5;
    const bool is_prod = (warp >= 8);
    const int g    = lane >> 2;        // 0..7
    const int t    = lane & 3;         // 0..3

    // Consumer mapping: 8 warps, warp tile 32 rows x 64 cols
    const int cwM = warp >> 1;         // 0..3 (only meaningful for warp<8)
    const int cwN = warp & 1;          // 0..1

    // Producer staging: ptid 0..255; row r, r+64; seg = 16 floats
    const int ptid = tid & 255;
    const int pr   = ptid >> 2;        // 0..63
    const int seg  = ptid & 3;         // 0..3

    // Consumer ldsm offsets
    const uint32_t aoff = (uint32_t)(cwM * 32 + (lane & 15)) * RSTR
                        + ((lane >> 4) & 1) * 16;
    const uint32_t boff = (uint32_t)(cwN * 64 + ((lane >> 4) & 1) * 8 + (lane & 7)) * RSTR
                        + ((lane >> 3) & 1) * 16;
    const uint32_t Adst[3] = {base + SM_A0, base + SM_A1, base + SM_A2};
    const uint32_t Wdst[4] = {base + SM_W0, base + SM_W1, base + SM_W2, base + SM_W3};
    const uint32_t Au3[3]  = {Adst[0] + aoff, Adst[1] + aoff, Adst[2] + aoff};
    const uint32_t Wu4[4]  = {Wdst[0] + boff, Wdst[1] + boff, Wdst[2] + boff, Wdst[3] + boff};

    // Score-GEMM offsets (all 16 warps): m16 x two n8 tiles (n0, n0+64)
    const int mq = (warp & 1) * 16;
    const int n0 = (warp >> 1) * 8;
    const uint32_t qa = base + SM_QBF + (uint32_t)(mq + (lane & 15)) * QSTR
                      + ((lane >> 4) & 1) * 16;
    const uint32_t da0 = base + SM_DBF + (uint32_t)(n0 + (lane & 7)) * QSTR
                       + ((lane >> 3) & 3) * 16;
    const uint32_t da1 = da0 + 64 * QSTR;

    // ---- In-kernel compaction (ballot) ----
    if (tid == 0) *cnt_s = 0;
    __syncthreads();
    for (int c = warp; c < 32; c += 16) {
        int j = c * 32 + lane;
        int v = attn[b * DL + j];
        unsigned m = __ballot_sync(0xffffffffu, v != 0);
        int bofs = 0;
        if (lane == 0) bofs = atomicAdd(cnt_s, __popc(m));
        bofs = __shfl_sync(0xffffffffu, bofs, 0);
        if (v != 0)
            idx_s[bofs + __popc(m & ((1u << lane) - 1u))] = j;
    }
    __syncthreads();
    const int nk = *cnt_s;
    const int ntiles = (nk + 32 + 127) >> 7;       // +32 virtual Q rows

    const float* Qrow = Qe   + (size_t)b * QL * HH;
    const float* Drow = Demb + (size_t)b * DL * HH;

    float lm0 = NEGV, lm1 = NEGV;

    for (int ti = 0; ti < ntiles; ti++) {
        const int vbase = ti * 128 - 32;

        float acc[2][8][4];
#pragma unroll
        for (int m = 0; m < 2; m++)
#pragma unroll
            for (int n = 0; n < 8; n++)
#pragma unroll
                for (int r = 0; r < 4; r++) acc[m][n][r] = 0.0f;

        if (is_prod) {
            // ---------------- PRODUCER ----------------
            const int v0 = vbase + pr;
            const int v1 = vbase + pr + 64;        // always >= 32 -> doc
            const float* a0p = (v0 < 0)
                ? Qrow + (size_t)pr * HH + seg * 16
                : Drow + (size_t)((v0 < nk) ? idx_s[v0] : 0) * HH + seg * 16;
            const float* a1p =
                  Drow + (size_t)((v1 < nk) ? idx_s[v1] : 0) * HH + seg * 16;

            float4 ra[2][8];
            // Prime: LDG chunks 0,1; cp.async W0, W1
#pragma unroll
            for (int c = 0; c < 2; c++) {
#pragma unroll
                for (int i = 0; i < 4; i++) {
                    ra[c][i]     = *(const float4*)(a0p + c * KC + i * 4);
                    ra[c][4 + i] = *(const float4*)(a1p + c * KC + i * 4);
                }
            }
#pragma unroll
            for (int c = 0; c < 2; c++) {
#pragma unroll
                for (int l = 0; l < 4; l++) {
                    int lin = ptid + l * 256;
                    int wr  = lin >> 3;
                    int c16 = lin & 7;
                    cp_async16(Wdst[c] + wr * RSTR + c16 * 16,
                               (const char*)g_Wbf + (size_t)wr * (HH * 2)
                                   + c * (KC * 2) + c16 * 16);
                }
                cp_commit();
            }

#pragma unroll
            for (int s = 0; s < NCHUNK; s++) {
                if (s >= 3) bar_sync_n(4 + s % 3);           // AE: A[s%3] free
                if (s <= 9) {                                 // issue W[s+2]
                    if (s >= 2) bar_sync_n(7 + (s + 2) % 4);  // WE: W buf free
                    uint32_t wdst = Wdst[(s + 2) % 4];
#pragma unroll
                    for (int l = 0; l < 4; l++) {
                        int lin = ptid + l * 256;
                        int wr  = lin >> 3;
                        int c16 = lin & 7;
                        cp_async16(wdst + wr * RSTR + c16 * 16,
                                   (const char*)g_Wbf + (size_t)wr * (HH * 2)
                                       + (s + 2) * (KC * 2) + c16 * 16);
                    }
                }
                cp_commit();        // uniform group count
                cp_wait2();         // W[s] complete
                // STS A chunk s
                const uint32_t ab  = Adst[s % 3] + (uint32_t)pr * RSTR + seg * 32;
                const uint32_t ab2 = ab + 64 * RSTR;
                const float4* r8 = ra[s & 1];
                sts128(ab,       f2bf2(r8[0].x, r8[0].y), f2bf2(r8[0].z, r8[0].w),
                                 f2bf2(r8[1].x, r8[1].y), f2bf2(r8[1].z, r8[1].w));
                sts128(ab + 16,  f2bf2(r8[2].x, r8[2].y), f2bf2(r8[2].z, r8[2].w),
                                 f2bf2(r8[3].x, r8[3].y), f2bf2(r8[3].z, r8[3].w));
                sts128(ab2,      f2bf2(r8[4].x, r8[4].y), f2bf2(r8[4].z, r8[4].w),
                                 f2bf2(r8[5].x, r8[5].y), f2bf2(r8[5].z, r8[5].w));
                sts128(ab2 + 16, f2bf2(r8[6].x, r8[6].y), f2bf2(r8[6].z, r8[6].w),
                                 f2bf2(r8[7].x, r8[7].y), f2bf2(r8[7].z, r8[7].w));
                bar_arrive_n(1 + s % 3);                      // AF: chunk s ready
                if (s + 2 < NCHUNK) {
#pragma unroll
                    for (int i = 0; i < 4; i++) {
                        ra[s & 1][i]     = *(const float4*)(a0p + (s + 2) * KC + i * 4);
                        ra[s & 1][4 + i] = *(const float4*)(a1p + (s + 2) * KC + i * 4);
                    }
                }
            }
        } else {
            // ---------------- CONSUMER ----------------
#pragma unroll
            for (int s = 0; s < NCHUNK; s++) {
                bar_sync_n(1 + s % 3);                        // AF: A[s],W[s] ready
                const uint32_t au = Au3[s % 3];
                const uint32_t wb = Wu4[s % 4];
#pragma unroll
                for (int kb = 0; kb < 4; kb++) {
                    uint32_t a0[4], a1[4];
                    ldsm_x4(a0, au + kb * 32);
                    ldsm_x4(a1, au + 16 * RSTR + kb * 32);
#pragma unroll
                    for (int j = 0; j < 4; j++) {
                        uint32_t bf[4];
                        ldsm_x4(bf, wb + j * 16 * RSTR + kb * 32);
                        mma_bf16(acc[0][2 * j],     a0, bf);
                        mma_bf16(acc[0][2 * j + 1], a0, bf + 2);
                        mma_bf16(acc[1][2 * j],     a1, bf);
                        mma_bf16(acc[1][2 * j + 1], a1, bf + 2);
                    }
                }
                if (s <= 8) bar_arrive_n(4 + s % 3);          // AE
                if (s <= 7) bar_arrive_n(7 + s % 4);          // WE
            }
        }

        // ---- Epilogue: consumers mask + row-norm partials ----
        if (!is_prod) {
#pragma unroll
            for (int m = 0; m < 2; m++) {
#pragma unroll
                for (int h = 0; h < 2; h++) {
                    int row = cwM * 32 + m * 16 + h * 8 + g;
                    int v   = vbase + row;
                    bool z  = false;
                    if (v >= 0 && v < nk) z = (ids[b * DL + idx_s[v]] == 0);
                    float s = 0.0f;
#pragma unroll
                    for (int n = 0; n < 8; n++) {
                        if (z) { acc[m][n][h * 2] = 0.0f; acc[m][n][h * 2 + 1] = 0.0f; }
                        float x = acc[m][n][h * 2];
                        float y = acc[m][n][h * 2 + 1];
                        s += x * x + y * y;
                    }
                    s += __shfl_xor_sync(0xffffffffu, s, 1, 4);
                    s += __shfl_xor_sync(0xffffffffu, s, 2, 4);
                    if (t == 0) rs[cwN * 128 + row] = s;
                }
            }
        }
        __syncthreads();

        // ---- Consumers: normalize -> Qbf (v<0) or Dbf; qsq/dsq ----
        if (!is_prod) {
#pragma unroll
            for (int m = 0; m < 2; m++) {
#pragma unroll
                for (int h = 0; h < 2; h++) {
                    int row   = cwM * 32 + m * 16 + h * 8 + g;
                    int v     = vbase + row;
                    float st  = rs[row] + rs[128 + row];
                    float inv = 1.0f / fmaxf(sqrtf(st), 1e-12f);
                    const bool isQ = (v < 0);
                    uint32_t dstb = isQ ? (base + SM_QBF) : (base + SM_DBF);
#pragma unroll
                    for (int n = 0; n < 8; n++) {
                        int col = cwN * 64 + n * 8 + t * 2;
                        uint32_t pk = f2bf2(acc[m][n][h * 2] * inv,
                                            acc[m][n][h * 2 + 1] * inv);
                        sts32(dstb + (uint32_t)row * QSTR + col * 2, pk);
                    }
                    if (cwN == 0 && t == 0) {
                        if (isQ) qsq[row] = st * inv * inv;
                        else     dsq[row] = st * inv * inv;
                    }
                }
            }
        }
        __syncthreads();

        // ---- Score GEMM (all 16 warps): two n8 tiles per warp ----
        {
            const float q0 = qsq[mq + g], q1 = qsq[mq + g + 8];
#pragma unroll
            for (int half = 0; half < 2; half++) {
                const uint32_t da = half ? da1 : da0;
                float sacc[4] = {0.0f, 0.0f, 0.0f, 0.0f};
#pragma unroll
                for (int kb = 0; kb < 8; kb += 2) {
                    uint32_t aA[4], aB[4], bb[4];
                    ldsm_x4(aA, qa + kb * 32);
                    ldsm_x4(aB, qa + (kb + 1) * 32);
                    ldsm_x4(bb, da + kb * 32);
                    mma_bf16(sacc, aA, bb);
                    mma_bf16(sacc, aB, bb + 2);
                }
                const int col0 = n0 + half * 64 + t * 2;
                const int col1 = col0 + 1;
                const int vc0  = vbase + col0;
                const int vc1  = vbase + col1;
                const bool k0  = (vc0 >= 0) && (vc0 < nk);
                const bool k1  = (vc1 >= 0) && (vc1 < nk);
                const float d0 = dsq[col0], d1 = dsq[col1];
                float s00 = k0 ? (2.0f * sacc[0] - q0 - d0) : NEGV;
                float s01 = k1 ? (2.0f * sacc[1] - q0 - d1) : NEGV;
                float s10 = k0 ? (2.0f * sacc[2] - q1 - d0) : NEGV;
                float s11 = k1 ? (2.0f * sacc[3] - q1 - d1) : NEGV;
                lm0 = fmaxf(lm0, fmaxf(s00, s01));
                lm1 = fmaxf(lm1, fmaxf(s10, s11));
            }
        }
        __syncthreads();   // Dbf/rs/buffers reuse next tile
    }

    // Final reductions
    lm0 = fmaxf(lm0, __shfl_xor_sync(0xffffffffu, lm0, 1));
    lm0 = fmaxf(lm0, __shfl_xor_sync(0xffffffffu, lm0, 2));
    lm1 = fmaxf(lm1, __shfl_xor_sync(0xffffffffu, lm1, 1));
    lm1 = fmaxf(lm1, __shfl_xor_sync(0xffffffffu, lm1, 2));
    if (t == 0) {
        int wc = warp >> 1;
        qpart[(mq + g) * 8 + wc]     = lm0;
        qpart[(mq + g + 8) * 8 + wc] = lm1;
    }
    __syncthreads();

    if (tid < 32) {
        float v = NEGV;
#pragma unroll
        for (int j = 0; j < 8; j++) v = fmaxf(v, qpart[tid * 8 + j]);
#pragma unroll
        for (int o = 16; o >= 1; o >>= 1) v += __shfl_xor_sync(0xffffffffu, v, o, 32);
        if (tid == 0) out[b] = v;
    }
}

// ---------------------------------------------------------------------------
extern "C" void kernel_launch(void* const* d_in, const int* in_sizes, int n_in,
                              void* d_out, int out_size)
{
    const float* Qe   = (const float*)d_in[0];  // [128,32,768]
    const float* De   = (const float*)d_in[1];  // [128,1024,768]
    const int*   ids  = (const int*)  d_in[2];  // [128,1024]
    const int*   attn = (const int*)  d_in[3];  // [128,1024]
    const float* W    = (const float*)d_in[4];  // [128,768]
    float*       out  = (float*)d_out;          // [128]

    wconv_kernel<<<(DIMD * HH) / (256 * 4), 256>>>(W);

    cudaFuncSetAttribute(score_kernel, cudaFuncAttributeMaxDynamicSharedMemorySize,
                         SM_TOTAL);
    score_kernel<<<BB, 512, SM_TOTAL>>>(De, Qe, ids, attn, out);
}